// round 15
// baseline (speedup 1.0000x reference)
#include <cuda_runtime.h>
#include <math.h>
#include <stdint.h>

#define DIM    768
#define BATCH  16
#define SEQ    1024
#define MTOK   (BATCH * SEQ)      // 16384
#define EPS    1e-5f

// ---------------------------------------------------------------------------
// Scratch (__device__ globals: allocation-guard safe)
// ---------------------------------------------------------------------------
__device__ float g_xAr[(size_t)MTOK * DIM];
__device__ float g_xBr[(size_t)MTOK * DIM];
__device__ float g_xCr[(size_t)MTOK * DIM];
__device__ float g_Wqr[(size_t)DIM * DIM];
__device__ float g_Wkr[(size_t)DIM * DIM];
__device__ float g_Wvr[(size_t)DIM * DIM];
__device__ float g_Wfcr[(size_t)DIM * DIM];
__device__ float g_Q  [(size_t)MTOK * DIM];
__device__ float g_KA [(size_t)MTOK * DIM];
__device__ float g_KB [(size_t)MTOK * DIM];
__device__ float g_VA [(size_t)MTOK * DIM];
__device__ float g_VB [(size_t)MTOK * DIM];
__device__ float g_VtA[(size_t)BATCH * DIM * SEQ];
__device__ float g_VtB[(size_t)BATCH * DIM * SEQ];
__device__ float g_S  [(size_t)BATCH * SEQ * SEQ];   // single branch: stays L2-resident
__device__ float g_iA [(size_t)MTOK * DIM];
__device__ float g_iB [(size_t)MTOK * DIM];
__device__ float g_h  [(size_t)MTOK * DIM];

// ---------------------------------------------------------------------------
// helpers
// ---------------------------------------------------------------------------
__device__ __forceinline__ uint32_t smem_u32(const void* p) {
    uint32_t a;
    asm("{ .reg .u64 t; cvta.to.shared.u64 t, %1; cvt.u32.u64 %0, t; }"
        : "=r"(a) : "l"(p));
    return a;
}
__device__ __forceinline__ uint32_t swz(uint32_t off) {
    return off ^ ((off >> 3) & 0x70);   // SW128 on 128B rows
}
__device__ __forceinline__ void cp_async16(uint32_t dst, const void* src) {
    asm volatile("cp.async.cg.shared.global [%0], [%1], 16;"
                 :: "r"(dst), "l"(src) : "memory");
}
__device__ __forceinline__ void cp_commit() {
    asm volatile("cp.async.commit_group;" ::: "memory");
}
template <int N>
__device__ __forceinline__ void cp_wait() {
    asm volatile("cp.async.wait_group %0;" :: "n"(N) : "memory");
}
__device__ __forceinline__ void ldsm_x4(uint32_t addr, uint32_t& r0, uint32_t& r1,
                                        uint32_t& r2, uint32_t& r3) {
    asm volatile("ldmatrix.sync.aligned.m8n8.x4.shared.b16 {%0,%1,%2,%3}, [%4];"
                 : "=r"(r0), "=r"(r1), "=r"(r2), "=r"(r3) : "r"(addr));
}
__device__ __forceinline__ float r32(float x) {
    uint32_t y;
    asm("cvt.rna.tf32.f32 %0, %1;" : "=r"(y) : "r"(__float_as_uint(x)));
    return __uint_as_float(y);
}
__device__ __forceinline__ void mma_tf32(float* c, const uint32_t* a,
                                         uint32_t b0, uint32_t b1) {
    asm volatile(
        "mma.sync.aligned.m16n8k8.row.col.f32.tf32.tf32.f32 "
        "{%0,%1,%2,%3}, {%4,%5,%6,%7}, {%8,%9}, {%0,%1,%2,%3};"
        : "+f"(c[0]), "+f"(c[1]), "+f"(c[2]), "+f"(c[3])
        : "r"(a[0]), "r"(a[1]), "r"(a[2]), "r"(a[3]), "r"(b0), "r"(b1));
}

// ---------------------------------------------------------------------------
// TF32 TN GEMM core — R13 pipeline skeleton + REGISTER FRAGMENT DOUBLE
// BUFFERING: while the mma stream consumes ks's fragments, the ldsm for
// ks+1 fills the alternate register buffer, removing the ldsm->mma
// dependency head from the critical path.
// C[M,N] = alpha * A · B^T (+bias) [ROUND: round output to tf32]
// BM=128, BN=256, BK=32.  8 warps (2x4), warp 64x64, 4-stage cp.async.
// 192KB dyn smem, 1 CTA/SM.
// ---------------------------------------------------------------------------
#define GBM 128
#define GBN 256
#define GBK 32
#define A_STG (GBM * 128)          // 16384 B
#define B_STG (GBN * 128)          // 32768 B
#define STG   (A_STG + B_STG)      // 49152 B
#define NSTAGE 4
#define GEMM_SMEM (NSTAGE * STG)   // 196608 B

template <bool ROUND>
__device__ __forceinline__ void gemm_core(const float* __restrict__ A,
                                          const float* __restrict__ B,
                                          int K,
                                          float* __restrict__ C, int ldc,
                                          const float* __restrict__ bias,
                                          float alpha)
{
    extern __shared__ char smem[];
    const uint32_t sbase = smem_u32(smem);
    const int tid  = threadIdx.x;
    const int wid  = tid >> 5;
    const int lane = tid & 31;
    const int warp_m = wid >> 2;        // 0..1  (64 rows each)
    const int warp_n = wid & 3;         // 0..3  (64 cols each)

    const int m0 = blockIdx.y * GBM;
    const int n0 = blockIdx.x * GBN;

    const int ld_row = tid >> 3;        // 0..31
    const int ld_cg  = tid & 7;         // 16B chunk within 128B row

    auto issue = [&](int c) {
        const uint32_t abase = sbase + (uint32_t)(c & 3) * STG;
        const uint32_t bbase = abase + A_STG;
        const float* Ak = A + (size_t)c * GBK;
        const float* Bk = B + (size_t)c * GBK;
#pragma unroll
        for (int i = 0; i < 4; ++i) {
            int r = ld_row + i * 32;
            cp_async16(abase + swz(r * 128 + ld_cg * 16),
                       Ak + (size_t)(m0 + r) * K + ld_cg * 4);
        }
#pragma unroll
        for (int i = 0; i < 8; ++i) {
            int r = ld_row + i * 32;
            cp_async16(bbase + swz(r * 128 + ld_cg * 16),
                       Bk + (size_t)(n0 + r) * K + ld_cg * 4);
        }
    };

    float acc[4][8][4];
#pragma unroll
    for (int i = 0; i < 4; ++i)
#pragma unroll
        for (int j = 0; j < 8; ++j)
#pragma unroll
            for (int k = 0; k < 4; ++k) acc[i][j][k] = 0.0f;

    const int nch = K / GBK;
#pragma unroll
    for (int s = 0; s < NSTAGE; ++s) { issue(s); cp_commit(); }

    // per-lane ldmatrix address components (lane l supplies row l&7 of matrix l>>3)
    const int mat = lane >> 3, r8 = lane & 7;
    const uint32_t a_off0 = (uint32_t)(warp_m * 64 + (mat & 1) * 8 + r8) * 128
                          + (uint32_t)(mat >> 1) * 16;
    const uint32_t b_off0 = (uint32_t)(warp_n * 64 + (mat >> 1) * 8 + r8) * 128
                          + (uint32_t)(mat & 1) * 16;

    for (int c = 0; c < nch; ++c) {
        cp_wait<NSTAGE - 2>();
        __syncthreads();
        const uint32_t abase = sbase + (uint32_t)(c & 3) * STG;
        const uint32_t bbase = abase + A_STG;

        uint32_t a[2][4][4], b[2][4][4];
        // prime ks=0 fragments into buffer 0
#pragma unroll
        for (int mi = 0; mi < 4; ++mi)
            ldsm_x4(abase + swz(a_off0 + mi * 16 * 128),
                    a[0][mi][0], a[0][mi][1], a[0][mi][2], a[0][mi][3]);
#pragma unroll
        for (int nj = 0; nj < 4; ++nj)
            ldsm_x4(bbase + swz(b_off0 + nj * 16 * 128),
                    b[0][nj][0], b[0][nj][1], b[0][nj][2], b[0][nj][3]);

#pragma unroll
        for (int ks = 0; ks < 4; ++ks) {
            const int cur = ks & 1, nxt = cur ^ 1;
            if (ks < 3) {
                // prefetch ks+1 fragments while the mma stream below runs
#pragma unroll
                for (int mi = 0; mi < 4; ++mi)
                    ldsm_x4(abase + swz(a_off0 + mi * 16 * 128 + (ks + 1) * 32),
                            a[nxt][mi][0], a[nxt][mi][1], a[nxt][mi][2], a[nxt][mi][3]);
#pragma unroll
                for (int nj = 0; nj < 4; ++nj)
                    ldsm_x4(bbase + swz(b_off0 + nj * 16 * 128 + (ks + 1) * 32),
                            b[nxt][nj][0], b[nxt][nj][1], b[nxt][nj][2], b[nxt][nj][3]);
            }
#pragma unroll
            for (int mi = 0; mi < 4; ++mi)
#pragma unroll
                for (int nj = 0; nj < 4; ++nj) {
                    mma_tf32(acc[mi][nj * 2 + 0], a[cur][mi], b[cur][nj][0], b[cur][nj][1]);
                    mma_tf32(acc[mi][nj * 2 + 1], a[cur][mi], b[cur][nj][2], b[cur][nj][3]);
                }
        }
        __syncthreads();
        if (c + NSTAGE < nch) issue(c + NSTAGE);
        cp_commit();
    }

    // ---- epilogue: warp writes its 64x64 tile
#pragma unroll
    for (int mi = 0; mi < 4; ++mi) {
        const int row = m0 + warp_m * 64 + mi * 16 + (lane >> 2);
#pragma unroll
        for (int nf = 0; nf < 8; ++nf) {
            const int col = n0 + warp_n * 64 + nf * 8 + (lane & 3) * 2;
            float bx = 0.0f, by = 0.0f;
            if (bias) { bx = bias[col]; by = bias[col + 1]; }
            float2 v0, v1;
            v0.x = acc[mi][nf][0] * alpha + bx;
            v0.y = acc[mi][nf][1] * alpha + by;
            v1.x = acc[mi][nf][2] * alpha + bx;
            v1.y = acc[mi][nf][3] * alpha + by;
            if (ROUND) {
                v0.x = r32(v0.x); v0.y = r32(v0.y);
                v1.x = r32(v1.x); v1.y = r32(v1.y);
            }
            *(float2*)(C + (size_t)row * ldc + col) = v0;
            *(float2*)(C + (size_t)(row + 8) * ldc + col) = v1;
        }
    }
}

// ---------------------------------------------------------------------------
// standalone GEMM (QK / PV / FC)
// ---------------------------------------------------------------------------
template <bool ROUND>
__global__ __launch_bounds__(256, 1)
void gemm_tf32(const float* __restrict__ A, long sA,
               const float* __restrict__ B, long sB,
               int K,
               float* __restrict__ C, int ldc, long sC,
               const float* __restrict__ bias, float alpha)
{
    A += (size_t)blockIdx.z * sA;
    B += (size_t)blockIdx.z * sB;
    C += (size_t)blockIdx.z * sC;
    gemm_core<ROUND>(A, B, K, C, ldc, bias, alpha);
}

// ---------------------------------------------------------------------------
// fused 5-projection GEMM: grid (3, 128, 5) = 1920 CTAs, tail ~0.2%.
// z: 0=Q(xC,Wq)  1=KA(xA,Wk)  2=KB(xB,Wk)  3=VA(xA,Wv)  4=VB(xB,Wv)
// ---------------------------------------------------------------------------
struct ProjArgs {
    const float *xA, *xB, *xC, *Wq, *Wk, *Wv;
    const float *bq, *bk, *bv;
    float *Q, *KA, *KB, *VA, *VB;
};

__global__ __launch_bounds__(256, 1)
void gemm_proj5(ProjArgs p)
{
    const float *A, *B, *bias; float* C;
    switch (blockIdx.z) {
        case 0:  A = p.xC; B = p.Wq; bias = p.bq; C = p.Q;  break;
        case 1:  A = p.xA; B = p.Wk; bias = p.bk; C = p.KA; break;
        case 2:  A = p.xB; B = p.Wk; bias = p.bk; C = p.KB; break;
        case 3:  A = p.xA; B = p.Wv; bias = p.bv; C = p.VA; break;
        default: A = p.xB; B = p.Wv; bias = p.bv; C = p.VB; break;
    }
    gemm_core<true>(A, B, DIM, C, DIM, bias, 1.0f);
}

// ---------------------------------------------------------------------------
// fused rounding (fp32 -> tf32-representable fp32), z-dispatched
// ---------------------------------------------------------------------------
__global__ __launch_bounds__(256)
void round3x(const float4* __restrict__ xA, const float4* __restrict__ xB,
             const float4* __restrict__ xC, float4* __restrict__ oA,
             float4* __restrict__ oB, float4* __restrict__ oC)
{
    const float4* in; float4* out;
    switch (blockIdx.z) {
        case 0:  in = xA; out = oA; break;
        case 1:  in = xB; out = oB; break;
        default: in = xC; out = oC; break;
    }
    const int i = blockIdx.x * 256 + threadIdx.x;
    float4 v = in[i];
    v.x = r32(v.x); v.y = r32(v.y); v.z = r32(v.z); v.w = r32(v.w);
    out[i] = v;
}

__global__ __launch_bounds__(256)
void round4w(const float4* __restrict__ Wq, const float4* __restrict__ Wk,
             const float4* __restrict__ Wv, const float4* __restrict__ Wfc,
             float4* __restrict__ oq, float4* __restrict__ ok,
             float4* __restrict__ ov, float4* __restrict__ ofc)
{
    const float4* in; float4* out;
    switch (blockIdx.z) {
        case 0:  in = Wq;  out = oq;  break;
        case 1:  in = Wk;  out = ok;  break;
        case 2:  in = Wv;  out = ov;  break;
        default: in = Wfc; out = ofc; break;
    }
    const int i = blockIdx.x * 256 + threadIdx.x;
    float4 v = in[i];
    v.x = r32(v.x); v.y = r32(v.y); v.z = r32(v.z); v.w = r32(v.w);
    out[i] = v;
}

// ---------------------------------------------------------------------------
// V [B][S][D] -> Vt [B][D][S]  (both branches in one launch via z)
// ---------------------------------------------------------------------------
__global__ __launch_bounds__(256)
void transpose2(const float* __restrict__ VA, const float* __restrict__ VB,
                float* __restrict__ OA, float* __restrict__ OB)
{
    __shared__ float tile[32][33];
    const int z = blockIdx.z, b = z & 15;
    const float* V = (z & 16) ? VB : VA;
    float* O = (z & 16) ? OB : OA;
    const int tx = threadIdx.x, ty = threadIdx.y;
    const int s0 = blockIdx.y * 32, d0 = blockIdx.x * 32;
    const float* Vb = V + (size_t)b * SEQ * DIM;
    float* Ob = O + (size_t)b * DIM * SEQ;
#pragma unroll
    for (int j = 0; j < 4; ++j)
        tile[ty + j * 8][tx] = Vb[(size_t)(s0 + ty + j * 8) * DIM + d0 + tx];
    __syncthreads();
#pragma unroll
    for (int j = 0; j < 4; ++j)
        Ob[(size_t)(d0 + ty + j * 8) * SEQ + s0 + tx] = tile[tx][ty + j * 8];
}

// ---------------------------------------------------------------------------
// row softmax over SEQ=1024 (in place, output rounded to tf32)
// ---------------------------------------------------------------------------
__global__ __launch_bounds__(256)
void softmax_kernel(float* __restrict__ S)
{
    __shared__ float red[8];
    float* row = S + (size_t)blockIdx.x * SEQ;
    const int t = threadIdx.x;

    float4 v = ((float4*)row)[t];
    float m = fmaxf(fmaxf(v.x, v.y), fmaxf(v.z, v.w));
#pragma unroll
    for (int o = 16; o; o >>= 1) m = fmaxf(m, __shfl_xor_sync(0xffffffffu, m, o));
    if ((t & 31) == 0) red[t >> 5] = m;
    __syncthreads();
    float bmax = red[0];
#pragma unroll
    for (int i = 1; i < 8; i++) bmax = fmaxf(bmax, red[i]);
    __syncthreads();

    v.x = __expf(v.x - bmax); v.y = __expf(v.y - bmax);
    v.z = __expf(v.z - bmax); v.w = __expf(v.w - bmax);
    float s = v.x + v.y + v.z + v.w;
#pragma unroll
    for (int o = 16; o; o >>= 1) s += __shfl_xor_sync(0xffffffffu, s, o);
    if ((t & 31) == 0) red[t >> 5] = s;
    __syncthreads();
    float tot = 0.0f;
#pragma unroll
    for (int i = 0; i < 8; i++) tot += red[i];
    const float inv = __frcp_rn(tot);

    v.x = r32(v.x * inv); v.y = r32(v.y * inv);
    v.z = r32(v.z * inv); v.w = r32(v.w * inv);
    ((float4*)row)[t] = v;
}

// ---------------------------------------------------------------------------
// h = LayerNorm(iA + iB + xC) * gamma + beta   (output rounded to tf32)
// ---------------------------------------------------------------------------
__global__ __launch_bounds__(256)
void add_ln_kernel(const float* __restrict__ iA, const float* __restrict__ iB,
                   const float* __restrict__ xC,
                   const float* __restrict__ gamma, const float* __restrict__ beta,
                   float* __restrict__ h)
{
    __shared__ float rs[8], rs2[8];
    const size_t base = (size_t)blockIdx.x * DIM;
    const int t = threadIdx.x;

    float x0 = iA[base + t]       + iB[base + t]       + xC[base + t];
    float x1 = iA[base + t + 256] + iB[base + t + 256] + xC[base + t + 256];
    float x2 = iA[base + t + 512] + iB[base + t + 512] + xC[base + t + 512];

    float s  = x0 + x1 + x2;
    float ss = x0 * x0 + x1 * x1 + x2 * x2;
#pragma unroll
    for (int o = 16; o; o >>= 1) {
        s  += __shfl_xor_sync(0xffffffffu, s,  o);
        ss += __shfl_xor_sync(0xffffffffu, ss, o);
    }
    if ((t & 31) == 0) { rs[t >> 5] = s; rs2[t >> 5] = ss; }
    __syncthreads();
    float S1 = 0.0f, S2 = 0.0f;
#pragma unroll
    for (int i = 0; i < 8; i++) { S1 += rs[i]; S2 += rs2[i]; }

    const float mu   = S1 * (1.0f / DIM);
    const float var  = S2 * (1.0f / DIM) - mu * mu;
    const float rstd = rsqrtf(var + EPS);

    h[base + t]       = r32((x0 - mu) * rstd * gamma[t]       + beta[t]);
    h[base + t + 256] = r32((x1 - mu) * rstd * gamma[t + 256] + beta[t + 256]);
    h[base + t + 512] = r32((x2 - mu) * rstd * gamma[t + 512] + beta[t + 512]);
}

// ---------------------------------------------------------------------------
// launch — R13 sequence (only the gemm_core fragment double-buffer changed)
// ---------------------------------------------------------------------------
extern "C" void kernel_launch(void* const* d_in, const int* in_sizes, int n_in,
                              void* d_out, int out_size)
{
    const float* xA    = (const float*)d_in[0];
    const float* xB    = (const float*)d_in[1];
    const float* xC    = (const float*)d_in[2];
    const float* Wq    = (const float*)d_in[3];
    const float* bq    = (const float*)d_in[4];
    const float* Wk    = (const float*)d_in[5];
    const float* bk    = (const float*)d_in[6];
    const float* Wv    = (const float*)d_in[7];
    const float* bv    = (const float*)d_in[8];
    const float* gamma = (const float*)d_in[9];
    const float* beta  = (const float*)d_in[10];
    const float* Wfc   = (const float*)d_in[11];
    const float* bfc   = (const float*)d_in[12];
    float* out = (float*)d_out;

    float *xAr, *xBr, *xCr, *Wqr, *Wkr, *Wvr, *Wfcr;
    float *Q, *KA, *KB, *VA, *VB, *VtA, *VtB, *Sf, *iA, *iB, *h;
    cudaGetSymbolAddress((void**)&xAr, g_xAr);
    cudaGetSymbolAddress((void**)&xBr, g_xBr);
    cudaGetSymbolAddress((void**)&xCr, g_xCr);
    cudaGetSymbolAddress((void**)&Wqr, g_Wqr);
    cudaGetSymbolAddress((void**)&Wkr, g_Wkr);
    cudaGetSymbolAddress((void**)&Wvr, g_Wvr);
    cudaGetSymbolAddress((void**)&Wfcr, g_Wfcr);
    cudaGetSymbolAddress((void**)&Q,   g_Q);
    cudaGetSymbolAddress((void**)&KA,  g_KA);
    cudaGetSymbolAddress((void**)&KB,  g_KB);
    cudaGetSymbolAddress((void**)&VA,  g_VA);
    cudaGetSymbolAddress((void**)&VB,  g_VB);
    cudaGetSymbolAddress((void**)&VtA, g_VtA);
    cudaGetSymbolAddress((void**)&VtB, g_VtB);
    cudaGetSymbolAddress((void**)&Sf,  g_S);
    cudaGetSymbolAddress((void**)&iA,  g_iA);
    cudaGetSymbolAddress((void**)&iB,  g_iB);
    cudaGetSymbolAddress((void**)&h,   g_h);

    cudaFuncSetAttribute(gemm_tf32<false>, cudaFuncAttributeMaxDynamicSharedMemorySize, GEMM_SMEM);
    cudaFuncSetAttribute(gemm_tf32<true>,  cudaFuncAttributeMaxDynamicSharedMemorySize, GEMM_SMEM);
    cudaFuncSetAttribute(gemm_proj5,       cudaFuncAttributeMaxDynamicSharedMemorySize, GEMM_SMEM);

    const float scale = 1.0f / sqrtf((float)DIM);
    const dim3 blk(256);
    const dim3 gqk(SEQ / GBN, SEQ / GBM, BATCH);    // (4, 8, 16)
    const dim3 gpv(DIM / GBN, SEQ / GBM, BATCH);    // (3, 8, 16)
    const long sQK = (long)SEQ * DIM;
    const long sSS = (long)SEQ * SEQ;
    const long sVT = (long)DIM * SEQ;

    // pre-round inputs + weights (fused: 2 launches)
    round3x<<<dim3(MTOK * DIM / 4 / 256, 1, 3), blk>>>(
        (const float4*)xA, (const float4*)xB, (const float4*)xC,
        (float4*)xAr, (float4*)xBr, (float4*)xCr);
    round4w<<<dim3(DIM * DIM / 4 / 256, 1, 4), blk>>>(
        (const float4*)Wq, (const float4*)Wk, (const float4*)Wv, (const float4*)Wfc,
        (float4*)Wqr, (float4*)Wkr, (float4*)Wvr, (float4*)Wfcr);

    // all 5 projections in ONE launch: grid (3, 128, 5) = 1920 CTAs (tail ~0.2%)
    ProjArgs pa;
    pa.xA = xAr; pa.xB = xBr; pa.xC = xCr;
    pa.Wq = Wqr; pa.Wk = Wkr; pa.Wv = Wvr;
    pa.bq = bq; pa.bk = bk; pa.bv = bv;
    pa.Q = Q; pa.KA = KA; pa.KB = KB; pa.VA = VA; pa.VB = VB;
    gemm_proj5<<<dim3(DIM / GBN, MTOK / GBM, 5), blk, GEMM_SMEM>>>(pa);

    // both V transposes (fused: 1 launch)
    transpose2<<<dim3(DIM / 32, SEQ / 32, 32), dim3(32, 8)>>>(VA, VB, VtA, VtB);

    // branch A: S = softmax(scale * Q K^T); iA = S @ V_A   (S stays 64MB, L2-resident)
    gemm_tf32<false><<<gqk, blk, GEMM_SMEM>>>(Q, sQK, KA, sQK, DIM, Sf, SEQ, sSS, nullptr, scale);
    softmax_kernel<<<BATCH * SEQ, blk>>>(Sf);
    gemm_tf32<false><<<gpv, blk, GEMM_SMEM>>>(Sf, sSS, VtA, sVT, SEQ, iA, DIM, sQK, nullptr, 1.0f);

    // branch B
    gemm_tf32<false><<<gqk, blk, GEMM_SMEM>>>(Q, sQK, KB, sQK, DIM, Sf, SEQ, sSS, nullptr, scale);
    softmax_kernel<<<BATCH * SEQ, blk>>>(Sf);
    gemm_tf32<false><<<gpv, blk, GEMM_SMEM>>>(Sf, sSS, VtB, sVT, SEQ, iB, DIM, sQK, nullptr, 1.0f);

    // residual + LN (rounded) + final FC
    add_ln_kernel<<<MTOK, blk>>>(iA, iB, xC, gamma, beta, h);
    gemm_tf32<false><<<dim3(DIM / GBN, MTOK / GBM, 1), blk, GEMM_SMEM>>>(
        h, 0, Wfcr, 0, DIM, out, DIM, 0, bfc, 1.0f);
}

// round 16
// speedup vs baseline: 1.0091x; 1.0091x over previous
#include <cuda_runtime.h>
#include <math.h>
#include <stdint.h>

#define DIM    768
#define BATCH  16
#define SEQ    1024
#define MTOK   (BATCH * SEQ)      // 16384
#define EPS    1e-5f

// ---------------------------------------------------------------------------
// Scratch (__device__ globals: allocation-guard safe)
// ---------------------------------------------------------------------------
__device__ float g_xAr[(size_t)MTOK * DIM];
__device__ float g_xBr[(size_t)MTOK * DIM];
__device__ float g_xCr[(size_t)MTOK * DIM];
__device__ float g_Wqr[(size_t)DIM * DIM];
__device__ float g_Wkr[(size_t)DIM * DIM];
__device__ float g_Wvr[(size_t)DIM * DIM];
__device__ float g_Wfcr[(size_t)DIM * DIM];
__device__ float g_Q  [(size_t)MTOK * DIM];
__device__ float g_KA [(size_t)MTOK * DIM];
__device__ float g_KB [(size_t)MTOK * DIM];
__device__ float g_VA [(size_t)MTOK * DIM];
__device__ float g_VB [(size_t)MTOK * DIM];
__device__ float g_VtA[(size_t)BATCH * DIM * SEQ];
__device__ float g_VtB[(size_t)BATCH * DIM * SEQ];
__device__ float g_S  [(size_t)BATCH * SEQ * SEQ];   // single branch: stays L2-resident
__device__ float g_iA [(size_t)MTOK * DIM];
__device__ float g_iB [(size_t)MTOK * DIM];
__device__ float g_h  [(size_t)MTOK * DIM];

// ---------------------------------------------------------------------------
// helpers
// ---------------------------------------------------------------------------
__device__ __forceinline__ uint32_t smem_u32(const void* p) {
    uint32_t a;
    asm("{ .reg .u64 t; cvta.to.shared.u64 t, %1; cvt.u32.u64 %0, t; }"
        : "=r"(a) : "l"(p));
    return a;
}
__device__ __forceinline__ uint32_t swz(uint32_t off) {
    return off ^ ((off >> 3) & 0x70);   // SW128 on 128B rows
}
__device__ __forceinline__ void cp_async16(uint32_t dst, const void* src) {
    asm volatile("cp.async.cg.shared.global [%0], [%1], 16;"
                 :: "r"(dst), "l"(src) : "memory");
}
__device__ __forceinline__ void cp_commit() {
    asm volatile("cp.async.commit_group;" ::: "memory");
}
template <int N>
__device__ __forceinline__ void cp_wait() {
    asm volatile("cp.async.wait_group %0;" :: "n"(N) : "memory");
}
__device__ __forceinline__ void ldsm_x4(uint32_t addr, uint32_t& r0, uint32_t& r1,
                                        uint32_t& r2, uint32_t& r3) {
    asm volatile("ldmatrix.sync.aligned.m8n8.x4.shared.b16 {%0,%1,%2,%3}, [%4];"
                 : "=r"(r0), "=r"(r1), "=r"(r2), "=r"(r3) : "r"(addr));
}
__device__ __forceinline__ float r32(float x) {
    uint32_t y;
    asm("cvt.rna.tf32.f32 %0, %1;" : "=r"(y) : "r"(__float_as_uint(x)));
    return __uint_as_float(y);
}
__device__ __forceinline__ void mma_tf32(float* c, const uint32_t* a,
                                         uint32_t b0, uint32_t b1) {
    asm volatile(
        "mma.sync.aligned.m16n8k8.row.col.f32.tf32.tf32.f32 "
        "{%0,%1,%2,%3}, {%4,%5,%6,%7}, {%8,%9}, {%0,%1,%2,%3};"
        : "+f"(c[0]), "+f"(c[1]), "+f"(c[2]), "+f"(c[3])
        : "r"(a[0]), "r"(a[1]), "r"(a[2]), "r"(a[3]), "r"(b0), "r"(b1));
}

// ---------------------------------------------------------------------------
// TF32 TN GEMM core — 2 CTAs/SM variant: BM=128, BN=128, BK=32, 3-stage
// cp.async (96KB smem/CTA), 8 warps (2x4), warp tile 64x32, ~120 regs.
// Two independent CTAs per SM cover each other's sync/issue/wait phases,
// which single-CTA scheduling tricks (R12/R14/R15) could not.
// C[M,N] = alpha * A · B^T (+bias) [ROUND: round output to tf32]
// ---------------------------------------------------------------------------
#define GBM 128
#define GBN 128
#define GBK 32
#define A_STG (GBM * 128)          // 16384 B
#define B_STG (GBN * 128)          // 16384 B
#define STG   (A_STG + B_STG)      // 32768 B
#define NSTAGE 3
#define GEMM_SMEM (NSTAGE * STG)   // 98304 B  (2 CTAs = 192KB <= 228KB)

template <bool ROUND>
__device__ __forceinline__ void gemm_core(const float* __restrict__ A,
                                          const float* __restrict__ B,
                                          int K,
                                          float* __restrict__ C, int ldc,
                                          const float* __restrict__ bias,
                                          float alpha)
{
    extern __shared__ char smem[];
    const uint32_t sbase = smem_u32(smem);
    const int tid  = threadIdx.x;
    const int wid  = tid >> 5;
    const int lane = tid & 31;
    const int warp_m = wid >> 2;        // 0..1  (64 rows each)
    const int warp_n = wid & 3;         // 0..3  (32 cols each)

    const int m0 = blockIdx.y * GBM;
    const int n0 = blockIdx.x * GBN;

    const int ld_row = tid >> 3;        // 0..31
    const int ld_cg  = tid & 7;         // 16B chunk within 128B row

    auto issue = [&](int c) {
        const uint32_t abase = sbase + (uint32_t)(c % 3) * STG;
        const uint32_t bbase = abase + A_STG;
        const float* Ak = A + (size_t)c * GBK;
        const float* Bk = B + (size_t)c * GBK;
#pragma unroll
        for (int i = 0; i < 4; ++i) {
            int r = ld_row + i * 32;
            cp_async16(abase + swz(r * 128 + ld_cg * 16),
                       Ak + (size_t)(m0 + r) * K + ld_cg * 4);
        }
#pragma unroll
        for (int i = 0; i < 4; ++i) {
            int r = ld_row + i * 32;
            cp_async16(bbase + swz(r * 128 + ld_cg * 16),
                       Bk + (size_t)(n0 + r) * K + ld_cg * 4);
        }
    };

    float acc[4][4][4];
#pragma unroll
    for (int i = 0; i < 4; ++i)
#pragma unroll
        for (int j = 0; j < 4; ++j)
#pragma unroll
            for (int k = 0; k < 4; ++k) acc[i][j][k] = 0.0f;

    const int nch = K / GBK;
#pragma unroll
    for (int s = 0; s < NSTAGE; ++s) { issue(s); cp_commit(); }

    // per-lane ldmatrix address components (lane l supplies row l&7 of matrix l>>3)
    const int mat = lane >> 3, r8 = lane & 7;
    const uint32_t a_off0 = (uint32_t)(warp_m * 64 + (mat & 1) * 8 + r8) * 128
                          + (uint32_t)(mat >> 1) * 16;
    const uint32_t b_off0 = (uint32_t)(warp_n * 32 + (mat >> 1) * 8 + r8) * 128
                          + (uint32_t)(mat & 1) * 16;

    for (int c = 0; c < nch; ++c) {
        cp_wait<NSTAGE - 2>();
        __syncthreads();
        const uint32_t abase = sbase + (uint32_t)(c % 3) * STG;
        const uint32_t bbase = abase + A_STG;

#pragma unroll
        for (int ks = 0; ks < 4; ++ks) {
            uint32_t a[4][4], b[2][4];
#pragma unroll
            for (int mi = 0; mi < 4; ++mi)
                ldsm_x4(abase + swz(a_off0 + mi * 16 * 128 + ks * 32),
                        a[mi][0], a[mi][1], a[mi][2], a[mi][3]);
#pragma unroll
            for (int nj = 0; nj < 2; ++nj)
                ldsm_x4(bbase + swz(b_off0 + nj * 16 * 128 + ks * 32),
                        b[nj][0], b[nj][1], b[nj][2], b[nj][3]);
#pragma unroll
            for (int mi = 0; mi < 4; ++mi)
#pragma unroll
                for (int nj = 0; nj < 2; ++nj) {
                    mma_tf32(acc[mi][nj * 2 + 0], a[mi], b[nj][0], b[nj][1]);
                    mma_tf32(acc[mi][nj * 2 + 1], a[mi], b[nj][2], b[nj][3]);
                }
        }
        __syncthreads();
        if (c + NSTAGE < nch) issue(c + NSTAGE);
        cp_commit();
    }

    // ---- epilogue: warp writes its 64x32 tile
#pragma unroll
    for (int mi = 0; mi < 4; ++mi) {
        const int row = m0 + warp_m * 64 + mi * 16 + (lane >> 2);
#pragma unroll
        for (int nf = 0; nf < 4; ++nf) {
            const int col = n0 + warp_n * 32 + nf * 8 + (lane & 3) * 2;
            float bx = 0.0f, by = 0.0f;
            if (bias) { bx = bias[col]; by = bias[col + 1]; }
            float2 v0, v1;
            v0.x = acc[mi][nf][0] * alpha + bx;
            v0.y = acc[mi][nf][1] * alpha + by;
            v1.x = acc[mi][nf][2] * alpha + bx;
            v1.y = acc[mi][nf][3] * alpha + by;
            if (ROUND) {
                v0.x = r32(v0.x); v0.y = r32(v0.y);
                v1.x = r32(v1.x); v1.y = r32(v1.y);
            }
            *(float2*)(C + (size_t)row * ldc + col) = v0;
            *(float2*)(C + (size_t)(row + 8) * ldc + col) = v1;
        }
    }
}

// ---------------------------------------------------------------------------
// standalone GEMM (QK / PV / FC)
// ---------------------------------------------------------------------------
template <bool ROUND>
__global__ __launch_bounds__(256, 2)
void gemm_tf32(const float* __restrict__ A, long sA,
               const float* __restrict__ B, long sB,
               int K,
               float* __restrict__ C, int ldc, long sC,
               const float* __restrict__ bias, float alpha)
{
    A += (size_t)blockIdx.z * sA;
    B += (size_t)blockIdx.z * sB;
    C += (size_t)blockIdx.z * sC;
    gemm_core<ROUND>(A, B, K, C, ldc, bias, alpha);
}

// ---------------------------------------------------------------------------
// fused 5-projection GEMM: grid (6, 128, 5) = 3840 CTAs.
// z: 0=Q(xC,Wq)  1=KA(xA,Wk)  2=KB(xB,Wk)  3=VA(xA,Wv)  4=VB(xB,Wv)
// ---------------------------------------------------------------------------
struct ProjArgs {
    const float *xA, *xB, *xC, *Wq, *Wk, *Wv;
    const float *bq, *bk, *bv;
    float *Q, *KA, *KB, *VA, *VB;
};

__global__ __launch_bounds__(256, 2)
void gemm_proj5(ProjArgs p)
{
    const float *A, *B, *bias; float* C;
    switch (blockIdx.z) {
        case 0:  A = p.xC; B = p.Wq; bias = p.bq; C = p.Q;  break;
        case 1:  A = p.xA; B = p.Wk; bias = p.bk; C = p.KA; break;
        case 2:  A = p.xB; B = p.Wk; bias = p.bk; C = p.KB; break;
        case 3:  A = p.xA; B = p.Wv; bias = p.bv; C = p.VA; break;
        default: A = p.xB; B = p.Wv; bias = p.bv; C = p.VB; break;
    }
    gemm_core<true>(A, B, DIM, C, DIM, bias, 1.0f);
}

// ---------------------------------------------------------------------------
// fused rounding (fp32 -> tf32-representable fp32), z-dispatched
// ---------------------------------------------------------------------------
__global__ __launch_bounds__(256)
void round3x(const float4* __restrict__ xA, const float4* __restrict__ xB,
             const float4* __restrict__ xC, float4* __restrict__ oA,
             float4* __restrict__ oB, float4* __restrict__ oC)
{
    const float4* in; float4* out;
    switch (blockIdx.z) {
        case 0:  in = xA; out = oA; break;
        case 1:  in = xB; out = oB; break;
        default: in = xC; out = oC; break;
    }
    const int i = blockIdx.x * 256 + threadIdx.x;
    float4 v = in[i];
    v.x = r32(v.x); v.y = r32(v.y); v.z = r32(v.z); v.w = r32(v.w);
    out[i] = v;
}

__global__ __launch_bounds__(256)
void round4w(const float4* __restrict__ Wq, const float4* __restrict__ Wk,
             const float4* __restrict__ Wv, const float4* __restrict__ Wfc,
             float4* __restrict__ oq, float4* __restrict__ ok,
             float4* __restrict__ ov, float4* __restrict__ ofc)
{
    const float4* in; float4* out;
    switch (blockIdx.z) {
        case 0:  in = Wq;  out = oq;  break;
        case 1:  in = Wk;  out = ok;  break;
        case 2:  in = Wv;  out = ov;  break;
        default: in = Wfc; out = ofc; break;
    }
    const int i = blockIdx.x * 256 + threadIdx.x;
    float4 v = in[i];
    v.x = r32(v.x); v.y = r32(v.y); v.z = r32(v.z); v.w = r32(v.w);
    out[i] = v;
}

// ---------------------------------------------------------------------------
// V [B][S][D] -> Vt [B][D][S]  (both branches in one launch via z)
// ---------------------------------------------------------------------------
__global__ __launch_bounds__(256)
void transpose2(const float* __restrict__ VA, const float* __restrict__ VB,
                float* __restrict__ OA, float* __restrict__ OB)
{
    __shared__ float tile[32][33];
    const int z = blockIdx.z, b = z & 15;
    const float* V = (z & 16) ? VB : VA;
    float* O = (z & 16) ? OB : OA;
    const int tx = threadIdx.x, ty = threadIdx.y;
    const int s0 = blockIdx.y * 32, d0 = blockIdx.x * 32;
    const float* Vb = V + (size_t)b * SEQ * DIM;
    float* Ob = O + (size_t)b * DIM * SEQ;
#pragma unroll
    for (int j = 0; j < 4; ++j)
        tile[ty + j * 8][tx] = Vb[(size_t)(s0 + ty + j * 8) * DIM + d0 + tx];
    __syncthreads();
#pragma unroll
    for (int j = 0; j < 4; ++j)
        Ob[(size_t)(d0 + ty + j * 8) * SEQ + s0 + tx] = tile[tx][ty + j * 8];
}

// ---------------------------------------------------------------------------
// row softmax over SEQ=1024 (in place, output rounded to tf32)
// ---------------------------------------------------------------------------
__global__ __launch_bounds__(256)
void softmax_kernel(float* __restrict__ S)
{
    __shared__ float red[8];
    float* row = S + (size_t)blockIdx.x * SEQ;
    const int t = threadIdx.x;

    float4 v = ((float4*)row)[t];
    float m = fmaxf(fmaxf(v.x, v.y), fmaxf(v.z, v.w));
#pragma unroll
    for (int o = 16; o; o >>= 1) m = fmaxf(m, __shfl_xor_sync(0xffffffffu, m, o));
    if ((t & 31) == 0) red[t >> 5] = m;
    __syncthreads();
    float bmax = red[0];
#pragma unroll
    for (int i = 1; i < 8; i++) bmax = fmaxf(bmax, red[i]);
    __syncthreads();

    v.x = __expf(v.x - bmax); v.y = __expf(v.y - bmax);
    v.z = __expf(v.z - bmax); v.w = __expf(v.w - bmax);
    float s = v.x + v.y + v.z + v.w;
#pragma unroll
    for (int o = 16; o; o >>= 1) s += __shfl_xor_sync(0xffffffffu, s, o);
    if ((t & 31) == 0) red[t >> 5] = s;
    __syncthreads();
    float tot = 0.0f;
#pragma unroll
    for (int i = 0; i < 8; i++) tot += red[i];
    const float inv = __frcp_rn(tot);

    v.x = r32(v.x * inv); v.y = r32(v.y * inv);
    v.z = r32(v.z * inv); v.w = r32(v.w * inv);
    ((float4*)row)[t] = v;
}

// ---------------------------------------------------------------------------
// h = LayerNorm(iA + iB + xC) * gamma + beta   (output rounded to tf32)
// ---------------------------------------------------------------------------
__global__ __launch_bounds__(256)
void add_ln_kernel(const float* __restrict__ iA, const float* __restrict__ iB,
                   const float* __restrict__ xC,
                   const float* __restrict__ gamma, const float* __restrict__ beta,
                   float* __restrict__ h)
{
    __shared__ float rs[8], rs2[8];
    const size_t base = (size_t)blockIdx.x * DIM;
    const int t = threadIdx.x;

    float x0 = iA[base + t]       + iB[base + t]       + xC[base + t];
    float x1 = iA[base + t + 256] + iB[base + t + 256] + xC[base + t + 256];
    float x2 = iA[base + t + 512] + iB[base + t + 512] + xC[base + t + 512];

    float s  = x0 + x1 + x2;
    float ss = x0 * x0 + x1 * x1 + x2 * x2;
#pragma unroll
    for (int o = 16; o; o >>= 1) {
        s  += __shfl_xor_sync(0xffffffffu, s,  o);
        ss += __shfl_xor_sync(0xffffffffu, ss, o);
    }
    if ((t & 31) == 0) { rs[t >> 5] = s; rs2[t >> 5] = ss; }
    __syncthreads();
    float S1 = 0.0f, S2 = 0.0f;
#pragma unroll
    for (int i = 0; i < 8; i++) { S1 += rs[i]; S2 += rs2[i]; }

    const float mu   = S1 * (1.0f / DIM);
    const float var  = S2 * (1.0f / DIM) - mu * mu;
    const float rstd = rsqrtf(var + EPS);

    h[base + t]       = r32((x0 - mu) * rstd * gamma[t]       + beta[t]);
    h[base + t + 256] = r32((x1 - mu) * rstd * gamma[t + 256] + beta[t + 256]);
    h[base + t + 512] = r32((x2 - mu) * rstd * gamma[t + 512] + beta[t + 512]);
}

// ---------------------------------------------------------------------------
// launch — R13 sequence; GEMM core swapped for the 2-CTA/SM variant
// ---------------------------------------------------------------------------
extern "C" void kernel_launch(void* const* d_in, const int* in_sizes, int n_in,
                              void* d_out, int out_size)
{
    const float* xA    = (const float*)d_in[0];
    const float* xB    = (const float*)d_in[1];
    const float* xC    = (const float*)d_in[2];
    const float* Wq    = (const float*)d_in[3];
    const float* bq    = (const float*)d_in[4];
    const float* Wk    = (const float*)d_in[5];
    const float* bk    = (const float*)d_in[6];
    const float* Wv    = (const float*)d_in[7];
    const float* bv    = (const float*)d_in[8];
    const float* gamma = (const float*)d_in[9];
    const float* beta  = (const float*)d_in[10];
    const float* Wfc   = (const float*)d_in[11];
    const float* bfc   = (const float*)d_in[12];
    float* out = (float*)d_out;

    float *xAr, *xBr, *xCr, *Wqr, *Wkr, *Wvr, *Wfcr;
    float *Q, *KA, *KB, *VA, *VB, *VtA, *VtB, *Sf, *iA, *iB, *h;
    cudaGetSymbolAddress((void**)&xAr, g_xAr);
    cudaGetSymbolAddress((void**)&xBr, g_xBr);
    cudaGetSymbolAddress((void**)&xCr, g_xCr);
    cudaGetSymbolAddress((void**)&Wqr, g_Wqr);
    cudaGetSymbolAddress((void**)&Wkr, g_Wkr);
    cudaGetSymbolAddress((void**)&Wvr, g_Wvr);
    cudaGetSymbolAddress((void**)&Wfcr, g_Wfcr);
    cudaGetSymbolAddress((void**)&Q,   g_Q);
    cudaGetSymbolAddress((void**)&KA,  g_KA);
    cudaGetSymbolAddress((void**)&KB,  g_KB);
    cudaGetSymbolAddress((void**)&VA,  g_VA);
    cudaGetSymbolAddress((void**)&VB,  g_VB);
    cudaGetSymbolAddress((void**)&VtA, g_VtA);
    cudaGetSymbolAddress((void**)&VtB, g_VtB);
    cudaGetSymbolAddress((void**)&Sf,  g_S);
    cudaGetSymbolAddress((void**)&iA,  g_iA);
    cudaGetSymbolAddress((void**)&iB,  g_iB);
    cudaGetSymbolAddress((void**)&h,   g_h);

    cudaFuncSetAttribute(gemm_tf32<false>, cudaFuncAttributeMaxDynamicSharedMemorySize, GEMM_SMEM);
    cudaFuncSetAttribute(gemm_tf32<true>,  cudaFuncAttributeMaxDynamicSharedMemorySize, GEMM_SMEM);
    cudaFuncSetAttribute(gemm_proj5,       cudaFuncAttributeMaxDynamicSharedMemorySize, GEMM_SMEM);

    const float scale = 1.0f / sqrtf((float)DIM);
    const dim3 blk(256);
    const dim3 gqk(SEQ / GBN, SEQ / GBM, BATCH);    // (8, 8, 16)
    const dim3 gpv(DIM / GBN, SEQ / GBM, BATCH);    // (6, 8, 16)
    const long sQK = (long)SEQ * DIM;
    const long sSS = (long)SEQ * SEQ;
    const long sVT = (long)DIM * SEQ;

    // pre-round inputs + weights (fused: 2 launches)
    round3x<<<dim3(MTOK * DIM / 4 / 256, 1, 3), blk>>>(
        (const float4*)xA, (const float4*)xB, (const float4*)xC,
        (float4*)xAr, (float4*)xBr, (float4*)xCr);
    round4w<<<dim3(DIM * DIM / 4 / 256, 1, 4), blk>>>(
        (const float4*)Wq, (const float4*)Wk, (const float4*)Wv, (const float4*)Wfc,
        (float4*)Wqr, (float4*)Wkr, (float4*)Wvr, (float4*)Wfcr);

    // all 5 projections in ONE launch: grid (6, 128, 5) = 3840 CTAs
    ProjArgs pa;
    pa.xA = xAr; pa.xB = xBr; pa.xC = xCr;
    pa.Wq = Wqr; pa.Wk = Wkr; pa.Wv = Wvr;
    pa.bq = bq; pa.bk = bk; pa.bv = bv;
    pa.Q = Q; pa.KA = KA; pa.KB = KB; pa.VA = VA; pa.VB = VB;
    gemm_proj5<<<dim3(DIM / GBN, MTOK / GBM, 5), blk, GEMM_SMEM>>>(pa);

    // both V transposes (fused: 1 launch)
    transpose2<<<dim3(DIM / 32, SEQ / 32, 32), dim3(32, 8)>>>(VA, VB, VtA, VtB);

    // branch A: S = softmax(scale * Q K^T); iA = S @ V_A   (S stays 64MB, L2-resident)
    gemm_tf32<false><<<gqk, blk, GEMM_SMEM>>>(Q, sQK, KA, sQK, DIM, Sf, SEQ, sSS, nullptr, scale);
    softmax_kernel<<<BATCH * SEQ, blk>>>(Sf);
    gemm_tf32<false><<<gpv, blk, GEMM_SMEM>>>(Sf, sSS, VtA, sVT, SEQ, iA, DIM, sQK, nullptr, 1.0f);

    // branch B
    gemm_tf32<false><<<gqk, blk, GEMM_SMEM>>>(Q, sQK, KB, sQK, DIM, Sf, SEQ, sSS, nullptr, scale);
    softmax_kernel<<<BATCH * SEQ, blk>>>(Sf);
    gemm_tf32<false><<<gpv, blk, GEMM_SMEM>>>(Sf, sSS, VtB, sVT, SEQ, iB, DIM, sQK, nullptr, 1.0f);

    // residual + LN (rounded) + final FC
    add_ln_kernel<<<MTOK, blk>>>(iA, iB, xC, gamma, beta, h);
    gemm_tf32<false><<<dim3(DIM / GBN, MTOK / GBM, 1), blk, GEMM_SMEM>>>(
        h, 0, Wfcr, 0, DIM, out, DIM, 0, bfc, 1.0f);
}